// round 1
// baseline (speedup 1.0000x reference)
#include <cuda_runtime.h>
#include <math.h>

#define DIM 128
#define TILE 128
#define BMAX 8192
#define NTILES_MAX (BMAX / TILE)

// Scratch (allocation-free rule: __device__ globals)
__device__ float g_nsk[BMAX];
__device__ float g_nim[BMAX];
__device__ float g_partial[BMAX * NTILES_MAX]; // row-sum of exp(-d) per (row, col-tile)
__device__ float g_diag[BMAX];                 // d(sk_i, im_i)
__device__ float g_rowval[BMAX];               // log(S_i) + d_ii

// ---------------------------------------------------------------------------
// Row squared norms: one warp per row (32 lanes x float4 = 128 floats)
// ---------------------------------------------------------------------------
__global__ void norms_kernel(const float* __restrict__ sk,
                             const float* __restrict__ im, int B) {
    int gwarp = (blockIdx.x * blockDim.x + threadIdx.x) >> 5;
    int lane = threadIdx.x & 31;
    if (gwarp >= B) return;
    const float* src = blockIdx.y ? im : sk;
    float* dst = blockIdx.y ? g_nim : g_nsk;
    float4 v = ((const float4*)(src + (size_t)gwarp * DIM))[lane];
    float s = v.x * v.x + v.y * v.y + v.z * v.z + v.w * v.w;
#pragma unroll
    for (int o = 16; o; o >>= 1) s += __shfl_xor_sync(0xffffffffu, s, o);
    if (lane == 0) dst[gwarp] = s;
}

// ---------------------------------------------------------------------------
// Fused GEMM + dist + exp + per-tile row reduction
// 128x128 tile, 256 threads, 8x8 per thread, BK=32
// ---------------------------------------------------------------------------
__global__ void __launch_bounds__(256, 2)
dist_kernel(const float* __restrict__ sk, const float* __restrict__ im,
            int B, int ntiles) {
    __shared__ float As[32][TILE];   // [k][m]
    __shared__ float Bs[32][TILE];   // [k][n]
    __shared__ float red[TILE][17];  // row-partial reduction, pad to kill conflicts

    const int bm = blockIdx.y;
    const int bn = blockIdx.x;
    const int tid = threadIdx.x;
    const int tx = tid & 15;   // 16 col-groups
    const int ty = tid >> 4;   // 16 row-groups

    const float* Ag = sk + (size_t)(bm * TILE) * DIM;
    const float* Bg = im + (size_t)(bn * TILE) * DIM;

    float acc[8][8];
#pragma unroll
    for (int i = 0; i < 8; i++)
#pragma unroll
        for (int j = 0; j < 8; j++) acc[i][j] = 0.f;

    for (int kk = 0; kk < DIM; kk += 32) {
        // Load 128 rows x 32 k of each operand, transposed into smem.
        // 1024 float4 loads per operand, 4 per thread, coalesced on global.
#pragma unroll
        for (int f0 = 0; f0 < 4; f0++) {
            int f = f0 * 256 + tid;        // 0..1023
            int m = f >> 3;                // row 0..127
            int k4 = (f & 7) << 2;         // k offset 0,4,...,28
            float4 a = *(const float4*)(Ag + m * DIM + kk + k4);
            As[k4 + 0][m] = a.x; As[k4 + 1][m] = a.y;
            As[k4 + 2][m] = a.z; As[k4 + 3][m] = a.w;
            float4 b = *(const float4*)(Bg + m * DIM + kk + k4);
            Bs[k4 + 0][m] = b.x; Bs[k4 + 1][m] = b.y;
            Bs[k4 + 2][m] = b.z; Bs[k4 + 3][m] = b.w;
        }
        __syncthreads();

#pragma unroll 4
        for (int k = 0; k < 32; k++) {
            float a[8], b[8];
            *(float4*)(a)     = *(const float4*)&As[k][ty * 8];
            *(float4*)(a + 4) = *(const float4*)&As[k][ty * 8 + 4];
            *(float4*)(b)     = *(const float4*)&Bs[k][tx * 8];
            *(float4*)(b + 4) = *(const float4*)&Bs[k][tx * 8 + 4];
#pragma unroll
            for (int i = 0; i < 8; i++)
#pragma unroll
                for (int j = 0; j < 8; j++) acc[i][j] = fmaf(a[i], b[j], acc[i][j]);
        }
        __syncthreads();
    }

    // Epilogue: sq -> d -> exp(-d), row partial sums; capture diagonal.
    float nr[8], nc[8];
#pragma unroll
    for (int r = 0; r < 8; r++) nr[r] = g_nsk[bm * TILE + ty * 8 + r];
#pragma unroll
    for (int c = 0; c < 8; c++) nc[c] = g_nim[bn * TILE + tx * 8 + c];

    float esum[8];
#pragma unroll
    for (int r = 0; r < 8; r++) {
        float s = 0.f;
#pragma unroll
        for (int c = 0; c < 8; c++) {
            float sq = nr[r] + nc[c] - 2.0f * acc[r][c];
            float d = sqrtf(fmaxf(sq, 0.f));
            s += __expf(-d);
            if (bm == bn && tx == ty && c == r) {
                g_diag[bm * TILE + ty * 8 + r] = d;
            }
        }
        esum[r] = s;
    }

#pragma unroll
    for (int r = 0; r < 8; r++) red[ty * 8 + r][tx] = esum[r];
    __syncthreads();

    if (tid < TILE) {
        float s = 0.f;
#pragma unroll
        for (int t = 0; t < 16; t++) s += red[tid][t];
        g_partial[(size_t)(bm * TILE + tid) * ntiles + bn] = s;
    }
}

// ---------------------------------------------------------------------------
// Per-row: log(sum of partials) + diag, fixed-order (deterministic)
// ---------------------------------------------------------------------------
__global__ void rows_kernel(int B, int ntiles) {
    int i = blockIdx.x * blockDim.x + threadIdx.x;
    if (i >= B) return;
    float s = 0.f;
    const float* p = g_partial + (size_t)i * ntiles;
    for (int t = 0; t < ntiles; t++) s += p[t];
    g_rowval[i] = logf(s) + g_diag[i];
}

// ---------------------------------------------------------------------------
// Final scalar reduce: single block, fixed tree (deterministic)
// ---------------------------------------------------------------------------
__global__ void final_kernel(float* __restrict__ out, int B, int out_size) {
    __shared__ float sm[1024];
    int tid = threadIdx.x;
    float s = 0.f;
    for (int i = tid; i < B; i += 1024) s += g_rowval[i];
    sm[tid] = s;
    __syncthreads();
    for (int o = 512; o; o >>= 1) {
        if (tid < o) sm[tid] += sm[tid + o];
        __syncthreads();
    }
    if (tid == 0) {
        float loss = sm[0] / (float)B;
        for (int i = 0; i < out_size; i++) out[i] = loss;
    }
}

extern "C" void kernel_launch(void* const* d_in, const int* in_sizes, int n_in,
                              void* d_out, int out_size) {
    const float* sk = (const float*)d_in[0];
    const float* im = (const float*)d_in[1];
    float* out = (float*)d_out;

    int B = in_sizes[0] / DIM;       // 8192
    int ntiles = B / TILE;           // 64

    dim3 nb((B + 7) / 8, 2);
    norms_kernel<<<nb, 256>>>(sk, im, B);

    dim3 grid(ntiles, ntiles);
    dist_kernel<<<grid, 256>>>(sk, im, B, ntiles);

    rows_kernel<<<(B + 255) / 256, 256>>>(B, ntiles);
    final_kernel<<<1, 1024>>>(out, B, out_size);
}

// round 3
// speedup vs baseline: 3.1006x; 3.1006x over previous
#include <cuda_runtime.h>
#include <cstdint>
#include <math.h>

#define DIM 128
#define TILE 128
#define BMAX 8192
#define NTMAX 64
#define TPB 4                 // B-tiles per CTA; A tile stays resident
#define LDR 132               // padded smem row (floats): banks (4g+t)%32 distinct

__device__ float g_nsk[BMAX];
__device__ float g_nim[BMAX];
__device__ float g_partial[(size_t)BMAX * NTMAX];
__device__ float g_diag[BMAX];
__device__ float g_rowval[BMAX];

static __device__ __forceinline__ uint32_t f2tf(float f) {
    uint32_t u;
    asm("cvt.rna.tf32.f32 %0, %1;" : "=r"(u) : "f"(f));
    return u;
}

static __device__ __forceinline__ void mma8(float* c, const uint32_t* a, const uint32_t* b) {
    asm("mma.sync.aligned.m16n8k8.row.col.f32.tf32.tf32.f32 "
        "{%0,%1,%2,%3}, {%4,%5,%6,%7}, {%8,%9}, {%0,%1,%2,%3};"
        : "+f"(c[0]), "+f"(c[1]), "+f"(c[2]), "+f"(c[3])
        : "r"(a[0]), "r"(a[1]), "r"(a[2]), "r"(a[3]), "r"(b[0]), "r"(b[1]));
}

// ---------------------------------------------------------------------------
// Row squared norms: one warp per row
// ---------------------------------------------------------------------------
__global__ void norms_kernel(const float* __restrict__ sk,
                             const float* __restrict__ im, int B) {
    int gwarp = (blockIdx.x * blockDim.x + threadIdx.x) >> 5;
    int lane = threadIdx.x & 31;
    if (gwarp >= B) return;
    const float* src = blockIdx.y ? im : sk;
    float* dst = blockIdx.y ? g_nim : g_nsk;
    float4 v = ((const float4*)(src + (size_t)gwarp * DIM))[lane];
    float s = v.x * v.x + v.y * v.y + v.z * v.z + v.w * v.w;
#pragma unroll
    for (int o = 16; o; o >>= 1) s += __shfl_xor_sync(0xffffffffu, s, o);
    if (lane == 0) dst[gwarp] = s;
}

// ---------------------------------------------------------------------------
// tf32 mma.sync GEMM + fused distance/exp epilogue.
// 256 threads = 8 warps (4 m-blocks x 2 n-blocks), warp tile 32x64.
// A tile resident; B double-buffered, prefetched in regs during epilogue.
// ---------------------------------------------------------------------------
__global__ void __launch_bounds__(256, 1)
dist_mma(const float* __restrict__ sk, const float* __restrict__ im, int nt) {
    extern __shared__ float smf[];
    float* As = smf;                           // 128*LDR
    float* Bs0 = smf + 128 * LDR;
    float* Bs1 = smf + 2 * 128 * LDR;
    float* red = smf + 3 * 128 * LDR;          // 256 floats

    const int tid = threadIdx.x;
    const int wid = tid >> 5;
    const int lane = tid & 31;
    const int g = lane >> 2;       // 0..7
    const int t = lane & 3;        // 0..3
    const int wm = wid & 3;        // m-block 0..3 (32 rows each)
    const int wn = wid >> 2;       // n-block 0..1 (64 cols each)

    const int ntg = nt / TPB;
    const int bm = blockIdx.x / ntg;
    const int bn0 = (blockIdx.x % ntg) * TPB;

    // ---- load A tile (cvt to tf32), and B tile 0 ----
    {
        const float4* Ag = (const float4*)(sk + (size_t)bm * TILE * DIM);
        const float4* Bg = (const float4*)(im + (size_t)bn0 * TILE * DIM);
#pragma unroll
        for (int it = 0; it < 16; it++) {
            int idx = it * 256 + tid;
            int m = idx >> 5, q4 = idx & 31;
            float4 va = Ag[idx];
            uint4 wa = {f2tf(va.x), f2tf(va.y), f2tf(va.z), f2tf(va.w)};
            *(uint4*)&As[m * LDR + q4 * 4] = wa;
            float4 vb = Bg[idx];
            uint4 wb = {f2tf(vb.x), f2tf(vb.y), f2tf(vb.z), f2tf(vb.w)};
            *(uint4*)&Bs0[m * LDR + q4 * 4] = wb;
        }
    }
    __syncthreads();

    // per-thread row norms (4 rows: mt in {0,1}, h in {0,1})
    float nr[2][2];
#pragma unroll
    for (int mt = 0; mt < 2; mt++)
#pragma unroll
        for (int h = 0; h < 2; h++)
            nr[mt][h] = g_nsk[bm * TILE + wm * 32 + mt * 16 + h * 8 + g];

    const int a_base = (wm * 32 + g) * LDR + t;
    const int b_base = (wn * 64 + g) * LDR + t;

    for (int tt = 0; tt < TPB; tt++) {
        const int bn = bn0 + tt;
        const float* Bsc = (tt & 1) ? Bs1 : Bs0;

        float acc[2][8][4];
#pragma unroll
        for (int mt = 0; mt < 2; mt++)
#pragma unroll
            for (int nb = 0; nb < 8; nb++)
#pragma unroll
                for (int r = 0; r < 4; r++) acc[mt][nb][r] = 0.f;

        // ---- MMA mainloop: 16 k-steps of 8 ----
#pragma unroll
        for (int ks = 0; ks < 16; ks++) {
            const int k = ks * 8;
            uint32_t a[2][4], b[8][2];
#pragma unroll
            for (int mt = 0; mt < 2; mt++) {
                int ba = a_base + mt * 16 * LDR + k;
                a[mt][0] = __float_as_uint(As[ba]);
                a[mt][1] = __float_as_uint(As[ba + 8 * LDR]);
                a[mt][2] = __float_as_uint(As[ba + 4]);
                a[mt][3] = __float_as_uint(As[ba + 8 * LDR + 4]);
            }
#pragma unroll
            for (int nb = 0; nb < 8; nb++) {
                int bb = b_base + nb * 8 * LDR + k;
                b[nb][0] = __float_as_uint(Bsc[bb]);
                b[nb][1] = __float_as_uint(Bsc[bb + 4]);
            }
#pragma unroll
            for (int mt = 0; mt < 2; mt++)
#pragma unroll
                for (int nb = 0; nb < 8; nb++) mma8(acc[mt][nb], a[mt], b[nb]);
        }

        // ---- prefetch next B tile into regs (hidden behind epilogue MUFU) ----
        float4 stg[16];
        if (tt < TPB - 1) {
            const float4* Bg = (const float4*)(im + (size_t)(bn + 1) * TILE * DIM);
#pragma unroll
            for (int it = 0; it < 16; it++) stg[it] = Bg[it * 256 + tid];
        }

        // ---- fused epilogue: sq -> d -> exp(-d), row partials ----
        const float2* ncp = (const float2*)(g_nim + (size_t)bn * TILE + wn * 64);
        const bool isdiag = (bm == bn);
#pragma unroll
        for (int mt = 0; mt < 2; mt++) {
#pragma unroll
            for (int h = 0; h < 2; h++) {
                const int r_local = wm * 32 + mt * 16 + h * 8 + g;
                float rs = 0.f;
#pragma unroll
                for (int nb = 0; nb < 8; nb++) {
                    float2 nc = ncp[nb * 4 + t];
                    float c0 = acc[mt][nb][h * 2 + 0];
                    float c1 = acc[mt][nb][h * 2 + 1];
                    float sq0 = fmaf(-2.f, c0, nr[mt][h] + nc.x);
                    float sq1 = fmaf(-2.f, c1, nr[mt][h] + nc.y);
                    sq0 = fmaxf(sq0, 1e-12f);
                    sq1 = fmaxf(sq1, 1e-12f);
                    float d0 = sq0 * rsqrtf(sq0);
                    float d1 = sq1 * rsqrtf(sq1);
                    rs += __expf(-d0) + __expf(-d1);
                    if (isdiag) {
                        int jc = wn * 64 + nb * 8 + 2 * t;
                        if (jc == r_local) g_diag[bm * TILE + r_local] = d0;
                        if (jc + 1 == r_local) g_diag[bm * TILE + r_local] = d1;
                    }
                }
                rs += __shfl_xor_sync(0xffffffffu, rs, 1);
                rs += __shfl_xor_sync(0xffffffffu, rs, 2);
                if (t == 0) red[r_local * 2 + wn] = rs;
            }
        }
        __syncthreads();
        if (tid < TILE)
            g_partial[(size_t)(bm * TILE + tid) * nt + bn] = red[tid * 2] + red[tid * 2 + 1];

        // ---- store staged B into the other buffer ----
        if (tt < TPB - 1) {
            float* Bn = (tt & 1) ? Bs0 : Bs1;
#pragma unroll
            for (int it = 0; it < 16; it++) {
                int idx = it * 256 + tid;
                int m = idx >> 5, q4 = idx & 31;
                uint4 w = {f2tf(stg[it].x), f2tf(stg[it].y), f2tf(stg[it].z), f2tf(stg[it].w)};
                *(uint4*)&Bn[m * LDR + q4 * 4] = w;
            }
        }
        __syncthreads();
    }
}

// ---------------------------------------------------------------------------
// Per-row: log(sum of partials) + diag (fixed order, deterministic)
// ---------------------------------------------------------------------------
__global__ void rows_kernel(int B, int ntiles) {
    int i = blockIdx.x * blockDim.x + threadIdx.x;
    if (i >= B) return;
    float s = 0.f;
    const float* p = g_partial + (size_t)i * ntiles;
    for (int t = 0; t < ntiles; t++) s += p[t];
    g_rowval[i] = logf(s) + g_diag[i];
}

__global__ void final_kernel(float* __restrict__ out, int B, int out_size) {
    __shared__ float sm[1024];
    int tid = threadIdx.x;
    float s = 0.f;
    for (int i = tid; i < B; i += 1024) s += g_rowval[i];
    sm[tid] = s;
    __syncthreads();
    for (int o = 512; o; o >>= 1) {
        if (tid < o) sm[tid] += sm[tid + o];
        __syncthreads();
    }
    if (tid == 0) {
        float loss = sm[0] / (float)B;
        for (int i = 0; i < out_size; i++) out[i] = loss;
    }
}

extern "C" void kernel_launch(void* const* d_in, const int* in_sizes, int n_in,
                              void* d_out, int out_size) {
    const float* sk = (const float*)d_in[0];
    const float* im = (const float*)d_in[1];
    float* out = (float*)d_out;

    int B = in_sizes[0] / DIM;   // 8192
    int nt = B / TILE;           // 64

    dim3 nb((B + 7) / 8, 2);
    norms_kernel<<<nb, 256>>>(sk, im, B);

    static const int SMEM_BYTES = (3 * 128 * LDR + 256) * 4;   // 203776
    cudaFuncSetAttribute(dist_mma, cudaFuncAttributeMaxDynamicSharedMemorySize, SMEM_BYTES);
    int ncta = nt * (nt / TPB);  // 1024
    dist_mma<<<ncta, 256, SMEM_BYTES>>>(sk, im, nt);

    rows_kernel<<<(B + 255) / 256, 256>>>(B, nt);
    final_kernel<<<1, 1024>>>(out, B, out_size);
}